// round 5
// baseline (speedup 1.0000x reference)
#include <cuda_runtime.h>
#include <cuda_bf16.h>

#define Bsz    64
#define Hd     1024
#define NV     101          // tokens incl. start symbol (start = 100)
#define UMX    256
#define NSTEPS 257
#define G3     3072         // 3*Hd
#define OD     1024
#define NCTA   128
#define NTHR   512
#define ETW    104          // embed-transpose padded width
#define KH     512          // k-half (2-way k split)
#define K2H    256          // k2 iterations per half (2 k per iter)

typedef unsigned long long u64;

// ---------------- static device scratch (no runtime allocation) ----------------
// Packed weights: g_Wp[mat][k2][jp][4] = {w[2k2][2jp], w[2k2][2jp+1], w[2k2+1][2jp], w[2k2+1][2jp+1]}
// mats: 0..2 = W_hh layer0 gates r,z,n; 3 = lin_W; 4..9 = layer1 (Wih r,z,n, Whh r,z,n); 10..15 = layer2.
__device__ __align__(16) float g_Wp[16 * 512 * 512 * 4];   // 64 MB
__device__ __align__(16) float g_T[NV * G3];               // layer0 gi table (incl. b_ih0)
__device__ __align__(16) float g_ET[Hd * ETW];             // embed transposed [k][v]
__device__ __align__(16) float g_st[2][3][Hd * Bsz];       // states k-major: [buf][layer][k*64+b]
__device__ unsigned g_bar;

// ---------------- grid barrier ----------------
__device__ __forceinline__ void gridbar() {
    __syncthreads();
    if (threadIdx.x == 0) {
        __threadfence();
        unsigned ticket = atomicAdd(&g_bar, 1u) + 1u;
        unsigned target = ((ticket + NCTA - 1u) / NCTA) * NCTA;
        while (*((volatile unsigned*)&g_bar) < target) { __nanosleep(32); }
    }
    __syncthreads();
    __threadfence();
}

// ---------------- packed f32x2 helpers ----------------
__device__ __forceinline__ u64 pk2(float v) {
    u64 r;
    asm("mov.b64 %0, {%1, %1};" : "=l"(r) : "f"(v));
    return r;
}
__device__ __forceinline__ void fma2(u64& d, u64 a, u64 b) {
    asm("fma.rn.f32x2 %0, %1, %2, %0;" : "+l"(d) : "l"(a), "l"(b));
}
__device__ __forceinline__ void add2(u64& d, u64 a) {
    asm("add.rn.f32x2 %0, %0, %1;" : "+l"(d) : "l"(a));
}
__device__ __forceinline__ float2 upk2(u64 v) {
    float lo, hi;
    asm("mov.b64 {%0, %1}, %2;" : "=f"(lo), "=f"(hi) : "l"(v));
    return make_float2(lo, hi);
}
__device__ __forceinline__ u64 lo64(const float4& v) { return *(const u64*)&v.x; }
__device__ __forceinline__ u64 hi64(const float4& v) { return *(const u64*)&v.z; }
__device__ __forceinline__ float sigm(float t) { return 1.0f / (1.0f + expf(-t)); }

// ================================================================================
__global__ void __launch_bounds__(NTHR, 1)
decoder_kernel(const int*   __restrict__ y,
               const float* __restrict__ embed,
               const float* __restrict__ W_ih,
               const float* __restrict__ W_hh,
               const float* __restrict__ b_ih,
               const float* __restrict__ b_hh,
               const float* __restrict__ init_state,
               const float* __restrict__ lin_W,
               const float* __restrict__ lin_b,
               float*       __restrict__ out)
{
    const int tid  = threadIdx.x;
    const int lane = tid & 31;
    const int wrp  = tid >> 5;               // 0..15
    const int t    = wrp & 7;                // tile slot
    const int kh   = wrp >> 3;               // k-half 0/1
    const int jp   = (blockIdx.x << 2) + (lane & 3);   // global j-pair 0..511
    const int j0   = jp << 1, j1 = j0 + 1;
    const int bb   = (t << 3) + (lane >> 2); // batch 0..63
    const int k2s  = kh * K2H;               // k2 start for this half
    const int gt   = blockIdx.x * NTHR + tid;

    __shared__ u64 s_red[8][32][6];          // 12 KB reduction buffer

    // ---------------- prologue 1: init states + transpose embed ----------------
    for (int idx = gt; idx < 3 * Hd * Bsz; idx += NCTA * NTHR) {
        int l = idx / (Hd * Bsz);
        int r = idx - l * (Hd * Bsz);
        g_st[1][l][r] = init_state[l * Hd + (r >> 6)];
    }
    for (int idx = gt; idx < Hd * ETW; idx += NCTA * NTHR) {
        int k = idx / ETW, v = idx - k * ETW;
        g_ET[idx] = (v < NV) ? embed[(size_t)v * Hd + k] : 0.0f;
    }
    gridbar();

    // ---------------- prologue 2a: weight repack into g_Wp ----------------
    for (int idx = gt; idx < 16 * 512 * 512; idx += NCTA * NTHR) {
        int mat = idx >> 18;
        int r   = idx & 262143;
        int k2  = r >> 9;
        int jpp = r & 511;
        const float* src;
        if (mat < 3)       src = W_hh + (size_t)mat * (Hd * Hd);
        else if (mat == 3) src = lin_W;
        else {
            int m  = mat - 4;
            int l  = (m / 6) + 1;
            int mm = m % 6;
            const float* base = (mm < 3) ? W_ih : W_hh;
            src = base + (size_t)l * G3 * Hd + (size_t)(mm % 3) * (Hd * Hd);
        }
        float2 r0 = *(const float2*)(src + (size_t)(2 * jpp)     * Hd + 2 * k2);
        float2 r1 = *(const float2*)(src + (size_t)(2 * jpp + 1) * Hd + 2 * k2);
        float4 v;
        v.x = r0.x; v.y = r1.x; v.z = r0.y; v.w = r1.y;
        *(((float4*)g_Wp) + idx) = v;
    }

    // ---------------- prologue 2b: token table T[v] = embed[v].Wih0^T + b_ih0 ----------------
    {
        const int jt = (blockIdx.x << 3) + t;
        const int vp = lane + kh * 32;
        if (vp < ETW / 2) {
            const int v0 = vp << 1;
            const float* w0 = W_ih + (size_t)jt * Hd;
            const float* w1 = W_ih + (size_t)(Hd + jt) * Hd;
            const float* w2 = W_ih + (size_t)(2 * Hd + jt) * Hd;
            u64 a0 = 0, a1 = 0, a2 = 0;
#pragma unroll 2
            for (int k = 0; k < Hd; k += 4) {
                float4 wa = *(const float4*)(w0 + k);
                float4 wb = *(const float4*)(w1 + k);
                float4 wc = *(const float4*)(w2 + k);
#pragma unroll
                for (int kk = 0; kk < 4; ++kk) {
                    u64 ev = *(const u64*)(g_ET + (size_t)(k + kk) * ETW + v0);
                    fma2(a0, pk2(((const float*)&wa)[kk]), ev);
                    fma2(a1, pk2(((const float*)&wb)[kk]), ev);
                    fma2(a2, pk2(((const float*)&wc)[kk]), ev);
                }
            }
            float2 t0 = upk2(a0), t1 = upk2(a1), t2 = upk2(a2);
            float br = b_ih[jt], bz = b_ih[Hd + jt], bn = b_ih[2 * Hd + jt];
            if (v0 < NV) {
                g_T[(size_t)v0 * G3 + jt]          = t0.x + br;
                g_T[(size_t)v0 * G3 + Hd + jt]     = t1.x + bz;
                g_T[(size_t)v0 * G3 + 2 * Hd + jt] = t2.x + bn;
            }
            if (v0 + 1 < NV) {
                g_T[(size_t)(v0 + 1) * G3 + jt]          = t0.y + br;
                g_T[(size_t)(v0 + 1) * G3 + Hd + jt]     = t1.y + bz;
                g_T[(size_t)(v0 + 1) * G3 + 2 * Hd + jt] = t2.y + bn;
            }
        }
    }
    gridbar();

    // weight base pointers for this lane (float offsets; 2048 floats per k2 row)
    const size_t wlane = (size_t)jp * 4;
    #define WMAT(m) (g_Wp + (((size_t)(m) * 512 + k2s) * 2048) + wlane)

    // ---------------- autoregressive step loop ----------------
    for (int u = 0; u < NSTEPS; ++u) {
        const int cur = u & 1, prv = cur ^ 1;

        // ===== phase A: layer0 Whh (mats 0..2) + output linear (mat 3) =====
        {
            const float* w0 = WMAT(0);
            const float* w1 = WMAT(1);
            const float* w2 = WMAT(2);
            const float* w3 = WMAT(3);
            const float* p0 = g_st[prv][0] + (size_t)(2 * k2s) * Bsz + bb;
            const float* p2 = g_st[prv][2] + (size_t)(2 * k2s) * Bsz + bb;
            u64 aR = 0, aZ = 0, aN = 0, aO = 0;
            float4 c0 = *(const float4*)w0;
            float4 c1 = *(const float4*)w1;
            float4 c2 = *(const float4*)w2;
            float4 c3 = *(const float4*)w3;
#pragma unroll 1
            for (int it = 0; it < K2H - 1; ++it) {
                float4 n0 = *(const float4*)(w0 += 2048);
                float4 n1 = *(const float4*)(w1 += 2048);
                float4 n2 = *(const float4*)(w2 += 2048);
                float4 n3 = *(const float4*)(w3 += 2048);
                u64 ph0 = pk2(p0[0]), ph1 = pk2(p0[64]);
                u64 po0 = pk2(p2[0]), po1 = pk2(p2[64]);
                fma2(aR, lo64(c0), ph0); fma2(aR, hi64(c0), ph1);
                fma2(aZ, lo64(c1), ph0); fma2(aZ, hi64(c1), ph1);
                fma2(aN, lo64(c2), ph0); fma2(aN, hi64(c2), ph1);
                fma2(aO, lo64(c3), po0); fma2(aO, hi64(c3), po1);
                c0 = n0; c1 = n1; c2 = n2; c3 = n3;
                p0 += 128; p2 += 128;
            }
            {
                u64 ph0 = pk2(p0[0]), ph1 = pk2(p0[64]);
                u64 po0 = pk2(p2[0]), po1 = pk2(p2[64]);
                fma2(aR, lo64(c0), ph0); fma2(aR, hi64(c0), ph1);
                fma2(aZ, lo64(c1), ph0); fma2(aZ, hi64(c1), ph1);
                fma2(aN, lo64(c2), ph0); fma2(aN, hi64(c2), ph1);
                fma2(aO, lo64(c3), po0); fma2(aO, hi64(c3), po1);
            }
            if (kh == 1) {
                s_red[t][lane][0] = aR; s_red[t][lane][1] = aZ;
                s_red[t][lane][2] = aN; s_red[t][lane][3] = aO;
            }
            __syncthreads();
            if (kh == 0) {
                add2(aR, s_red[t][lane][0]);
                add2(aZ, s_red[t][lane][1]);
                add2(aN, s_red[t][lane][2]);
                add2(aO, s_red[t][lane][3]);
                int tk = (u == 0) ? (NV - 1) : y[bb * UMX + (u - 1)];
                const float* Tv = g_T + (size_t)tk * G3;
                float2 gr = upk2(*(const u64*)(Tv + j0));
                float2 gz = upk2(*(const u64*)(Tv + Hd + j0));
                float2 gn = upk2(*(const u64*)(Tv + 2 * Hd + j0));
                float2 ghr = upk2(aR), ghz = upk2(aZ), ghn = upk2(aN);
                const float* hp0 = g_st[prv][0];
                float ho0 = hp0[(size_t)j0 * Bsz + bb];
                float ho1 = hp0[(size_t)j1 * Bsz + bb];
                {
                    float r = sigm(gr.x + ghr.x + b_hh[j0]);
                    float z = sigm(gz.x + ghz.x + b_hh[Hd + j0]);
                    float n = tanhf(gn.x + r * (ghn.x + b_hh[2 * Hd + j0]));
                    g_st[cur][0][(size_t)j0 * Bsz + bb] = (1.0f - z) * n + z * ho0;
                }
                {
                    float r = sigm(gr.y + ghr.y + b_hh[j1]);
                    float z = sigm(gz.y + ghz.y + b_hh[Hd + j1]);
                    float n = tanhf(gn.y + r * (ghn.y + b_hh[2 * Hd + j1]));
                    g_st[cur][0][(size_t)j1 * Bsz + bb] = (1.0f - z) * n + z * ho1;
                }
                if (u > 0) {
                    float2 o = upk2(aO);
                    o.x += lin_b[j0]; o.y += lin_b[j1];
                    *(float2*)(out + (size_t)bb * NSTEPS * OD + (size_t)(u - 1) * OD + j0) = o;
                }
            }
        }
        gridbar();

        // ===== phases B, C: layers 1, 2 (mats base 4 / 10) =====
#pragma unroll 1
        for (int l = 1; l < 3; ++l) {
            const int mb = 4 + (l - 1) * 6;
            const float* w0 = WMAT(mb + 0);   // Wih r
            const float* w1 = WMAT(mb + 1);   // Wih z
            const float* w2 = WMAT(mb + 2);   // Wih n
            const float* w3 = WMAT(mb + 3);   // Whh r
            const float* w4 = WMAT(mb + 4);   // Whh z
            const float* w5 = WMAT(mb + 5);   // Whh n
            const float* px = g_st[cur][l - 1] + (size_t)(2 * k2s) * Bsz + bb;
            const float* ph = g_st[prv][l]     + (size_t)(2 * k2s) * Bsz + bb;
            u64 iR = 0, iZ = 0, iN = 0, hR = 0, hZ = 0, hN = 0;
            float4 c0 = *(const float4*)w0;
            float4 c1 = *(const float4*)w1;
            float4 c2 = *(const float4*)w2;
            float4 c3 = *(const float4*)w3;
            float4 c4 = *(const float4*)w4;
            float4 c5 = *(const float4*)w5;
#pragma unroll 1
            for (int it = 0; it < K2H - 1; ++it) {
                float4 n0 = *(const float4*)(w0 += 2048);
                float4 n1 = *(const float4*)(w1 += 2048);
                float4 n2 = *(const float4*)(w2 += 2048);
                float4 n3 = *(const float4*)(w3 += 2048);
                float4 n4 = *(const float4*)(w4 += 2048);
                float4 n5 = *(const float4*)(w5 += 2048);
                u64 x0 = pk2(px[0]), x1 = pk2(px[64]);
                u64 h0 = pk2(ph[0]), h1 = pk2(ph[64]);
                fma2(iR, lo64(c0), x0); fma2(iR, hi64(c0), x1);
                fma2(iZ, lo64(c1), x0); fma2(iZ, hi64(c1), x1);
                fma2(iN, lo64(c2), x0); fma2(iN, hi64(c2), x1);
                fma2(hR, lo64(c3), h0); fma2(hR, hi64(c3), h1);
                fma2(hZ, lo64(c4), h0); fma2(hZ, hi64(c4), h1);
                fma2(hN, lo64(c5), h0); fma2(hN, hi64(c5), h1);
                c0 = n0; c1 = n1; c2 = n2; c3 = n3; c4 = n4; c5 = n5;
                px += 128; ph += 128;
            }
            {
                u64 x0 = pk2(px[0]), x1 = pk2(px[64]);
                u64 h0 = pk2(ph[0]), h1 = pk2(ph[64]);
                fma2(iR, lo64(c0), x0); fma2(iR, hi64(c0), x1);
                fma2(iZ, lo64(c1), x0); fma2(iZ, hi64(c1), x1);
                fma2(iN, lo64(c2), x0); fma2(iN, hi64(c2), x1);
                fma2(hR, lo64(c3), h0); fma2(hR, hi64(c3), h1);
                fma2(hZ, lo64(c4), h0); fma2(hZ, hi64(c4), h1);
                fma2(hN, lo64(c5), h0); fma2(hN, hi64(c5), h1);
            }
            if (kh == 1) {
                s_red[t][lane][0] = iR; s_red[t][lane][1] = iZ; s_red[t][lane][2] = iN;
                s_red[t][lane][3] = hR; s_red[t][lane][4] = hZ; s_red[t][lane][5] = hN;
            }
            __syncthreads();
            if (kh == 0) {
                add2(iR, s_red[t][lane][0]);
                add2(iZ, s_red[t][lane][1]);
                add2(iN, s_red[t][lane][2]);
                add2(hR, s_red[t][lane][3]);
                add2(hZ, s_red[t][lane][4]);
                add2(hN, s_red[t][lane][5]);
                float2 gir = upk2(iR), giz = upk2(iZ), gin = upk2(iN);
                float2 ghr = upk2(hR), ghz = upk2(hZ), ghn = upk2(hN);
                const float* bi = b_ih + l * G3;
                const float* bh = b_hh + l * G3;
                const float* hps = g_st[prv][l];
                float ho0 = hps[(size_t)j0 * Bsz + bb];
                float ho1 = hps[(size_t)j1 * Bsz + bb];
                {
                    float r = sigm(gir.x + bi[j0] + ghr.x + bh[j0]);
                    float z = sigm(giz.x + bi[Hd + j0] + ghz.x + bh[Hd + j0]);
                    float n = tanhf(gin.x + bi[2 * Hd + j0] + r * (ghn.x + bh[2 * Hd + j0]));
                    g_st[cur][l][(size_t)j0 * Bsz + bb] = (1.0f - z) * n + z * ho0;
                }
                {
                    float r = sigm(gir.y + bi[j1] + ghr.y + bh[j1]);
                    float z = sigm(giz.y + bi[Hd + j1] + ghz.y + bh[Hd + j1]);
                    float n = tanhf(gin.y + bi[2 * Hd + j1] + r * (ghn.y + bh[2 * Hd + j1]));
                    g_st[cur][l][(size_t)j1 * Bsz + bb] = (1.0f - z) * n + z * ho1;
                }
            }
            gridbar();
        }
    }

    // ---------------- final output flush (step NSTEPS-1, state buf 0) ----------------
    {
        const float* w3 = WMAT(3);
        const float* p2 = g_st[0][2] + (size_t)(2 * k2s) * Bsz + bb;
        u64 aO = 0;
#pragma unroll 2
        for (int it = 0; it < K2H; ++it) {
            float4 c = *(const float4*)w3;
            fma2(aO, lo64(c), pk2(p2[0]));
            fma2(aO, hi64(c), pk2(p2[64]));
            w3 += 2048; p2 += 128;
        }
        if (kh == 1) s_red[t][lane][0] = aO;
        __syncthreads();
        if (kh == 0) {
            add2(aO, s_red[t][lane][0]);
            float2 o = upk2(aO);
            o.x += lin_b[j0]; o.y += lin_b[j1];
            *(float2*)(out + (size_t)bb * NSTEPS * OD + (size_t)(NSTEPS - 1) * OD + j0) = o;
        }
    }
    #undef WMAT
}

extern "C" void kernel_launch(void* const* d_in, const int* in_sizes, int n_in,
                              void* d_out, int out_size) {
    (void)in_sizes; (void)n_in; (void)out_size;
    const int*   y          = (const int*)  d_in[0];
    // d_in[1] = U (unused by the reference math)
    const float* embed      = (const float*)d_in[2];
    const float* W_ih       = (const float*)d_in[3];
    const float* W_hh       = (const float*)d_in[4];
    const float* b_ih       = (const float*)d_in[5];
    const float* b_hh       = (const float*)d_in[6];
    const float* init_state = (const float*)d_in[7];
    const float* lin_W      = (const float*)d_in[8];
    const float* lin_b      = (const float*)d_in[9];
    float* out = (float*)d_out;

    decoder_kernel<<<NCTA, NTHR>>>(y, embed, W_ih, W_hh, b_ih, b_hh,
                                   init_state, lin_W, lin_b, out);
}

// round 6
// speedup vs baseline: 1.1040x; 1.1040x over previous
#include <cuda_runtime.h>
#include <cuda_bf16.h>

#define Bsz    64
#define Hd     1024
#define NV     101          // tokens incl. start symbol (start = 100)
#define UMX    256
#define NSTEPS 257
#define G3     3072
#define NCTA   128
#define NTHR   512

typedef unsigned u32;

// ---------------- static device scratch (no runtime allocation) ----------------
// Phase A weights: rows 0..3071 = W_hh layer0 (gates r,z,n), rows 3072..4095 = lin_W. K=1024.
__device__ __align__(16) __nv_bfloat16 g_W0h[4096 * 1024];
__device__ __align__(16) __nv_bfloat16 g_W0l[4096 * 1024];
// Phase B/C weights per layer l in {1,2}: 4096 rows x K=2048.
//  row q*1024+j: q=0: [Wih_r | Whh_r]; q=1: [Wih_z | Whh_z]; q=2: [Wih_n | 0]; q=3: [0 | Whh_n]
__device__ __align__(16) __nv_bfloat16 g_W12h[2 * 4096 * 2048];
__device__ __align__(16) __nv_bfloat16 g_W12l[2 * 4096 * 2048];
// Activations bf16 hi/lo: [l(3)][parity(2)][b(64)][c(2048)]
//  l=0: cols 0..1023 = h0 ; l=1,2: cols 0..1023 = x (prev layer out), 1024..2047 = h_prev
__device__ __align__(16) __nv_bfloat16 g_Ahi[3 * 2 * 64 * 2048];
__device__ __align__(16) __nv_bfloat16 g_Alo[3 * 2 * 64 * 2048];
__device__ __align__(16) float g_T[NV * G3];          // layer0 gi table (incl b_ih0), fp32
__device__ __align__(16) float g_stf[3 * 64 * 1024];  // fp32 states [l][b][j]
__device__ unsigned g_bar;

#define AIDX(l, par, b, c) (((((l) * 2 + (par)) * 64 + (b)) << 11) + (c))

// ---------------- grid barrier (128 CTAs, 1/SM, co-resident) ----------------
__device__ __forceinline__ void gridbar() {
    __threadfence();
    __syncthreads();
    if (threadIdx.x == 0) {
        unsigned ticket = atomicAdd(&g_bar, 1u) + 1u;
        unsigned target = ((ticket + NCTA - 1u) / NCTA) * NCTA;
        while (*((volatile unsigned*)&g_bar) < target) { __nanosleep(32); }
    }
    __syncthreads();
    __threadfence();
}

__device__ __forceinline__ float sigm(float t) { return 1.0f / (1.0f + expf(-t)); }
__device__ __forceinline__ void bsplit(float v, __nv_bfloat16& h, __nv_bfloat16& l) {
    h = __float2bfloat16(v);
    l = __float2bfloat16(v - __bfloat162float(h));
}

// ---------------- mma.m16n8k16 bf16 fragments ----------------
struct AF { u32 r0, r1, r2, r3; };
struct BF { u32 r0, r1; };

__device__ __forceinline__ void mma_bf16(float* d, const AF& a, const BF& b) {
    asm volatile(
        "mma.sync.aligned.m16n8k16.row.col.f32.bf16.bf16.f32 "
        "{%0,%1,%2,%3}, {%4,%5,%6,%7}, {%8,%9}, {%0,%1,%2,%3};"
        : "+f"(d[0]), "+f"(d[1]), "+f"(d[2]), "+f"(d[3])
        : "r"(a.r0), "r"(a.r1), "r"(a.r2), "r"(a.r3), "r"(b.r0), "r"(b.r1));
}
__device__ __forceinline__ void ldA(AF& f, const __nv_bfloat16* p0, const __nv_bfloat16* p1) {
    f.r0 = *(const u32*)p0;       f.r1 = *(const u32*)p1;
    f.r2 = *(const u32*)(p0 + 8); f.r3 = *(const u32*)(p1 + 8);
}
__device__ __forceinline__ void ldB(BF& f, const __nv_bfloat16* p) {
    f.r0 = *(const u32*)p; f.r1 = *(const u32*)(p + 8);
}

// K-loop: D = A x W^T over `tiles` k16-tiles, bf16x3 split, 3 independent accums.
// aH/aL pre-offset to (m-row 0 of warp tile, k begin); wH/wL pre-offset to (n-row 0, k begin).
__device__ __forceinline__ void run_gemm(
    const __nv_bfloat16* __restrict__ aH, const __nv_bfloat16* __restrict__ aL,
    const __nv_bfloat16* __restrict__ wH, const __nv_bfloat16* __restrict__ wL,
    int wRS, int tiles, int lane, float* dhh, float* dhl, float* dlh)
{
    const int quad = lane >> 2, c2 = (lane & 3) << 1;
    const __nv_bfloat16* pAh0 = aH + quad * 2048 + c2;
    const __nv_bfloat16* pAh1 = pAh0 + 8 * 2048;
    const __nv_bfloat16* pAl0 = aL + quad * 2048 + c2;
    const __nv_bfloat16* pAl1 = pAl0 + 8 * 2048;
    const __nv_bfloat16* pBh  = wH + quad * wRS + c2;
    const __nv_bfloat16* pBl  = wL + quad * wRS + c2;
    AF a0h, a0l, a1h, a1l; BF b0h, b0l, b1h, b1l;
#define LOADS(AH, AL, BH, BL) do { \
        ldA(AH, pAh0, pAh1); ldA(AL, pAl0, pAl1); ldB(BH, pBh); ldB(BL, pBl); \
        pAh0 += 16; pAh1 += 16; pAl0 += 16; pAl1 += 16; pBh += 16; pBl += 16; } while (0)
#define MMAS(AH, AL, BH, BL) do { \
        mma_bf16(dhh, AH, BH); mma_bf16(dhl, AH, BL); mma_bf16(dlh, AL, BH); } while (0)
    LOADS(a0h, a0l, b0h, b0l);
#pragma unroll 1
    for (int t = 0; t < tiles - 2; t += 2) {
        LOADS(a1h, a1l, b1h, b1l);
        MMAS(a0h, a0l, b0h, b0l);
        LOADS(a0h, a0l, b0h, b0l);
        MMAS(a1h, a1l, b1h, b1l);
    }
    LOADS(a1h, a1l, b1h, b1l);
    MMAS(a0h, a0l, b0h, b0l);
    MMAS(a1h, a1l, b1h, b1l);
#undef LOADS
#undef MMAS
}

// ================================================================================
__global__ void __launch_bounds__(NTHR, 1)
decoder_kernel(const int*   __restrict__ y,
               const float* __restrict__ embed,
               const float* __restrict__ W_ih,
               const float* __restrict__ W_hh,
               const float* __restrict__ b_ih,
               const float* __restrict__ b_hh,
               const float* __restrict__ init_state,
               const float* __restrict__ lin_W,
               const float* __restrict__ lin_b,
               float*       __restrict__ out)
{
    const int tid  = threadIdx.x;
    const int lane = tid & 31;
    const int wid  = tid >> 5;          // 0..15
    const int mw   = wid & 3;           // m-tile index
    const int q    = wid >> 2;          // n-group: 0=r 1=z 2=in 3=hn (phaseA: 0..2=gates, 3=lin)
    const int m0   = mw << 4;
    const int cta  = blockIdx.x;
    const int gt   = cta * NTHR + tid;
    const int GS   = NCTA * NTHR;

    __shared__ float sD[4][4][16][8];   // [m][q][row][col] 8 KB

    // ================= PROLOGUE =================
    // phase A weights (K=1024): W_hh layer0 + lin_W
    for (int idx = gt; idx < 4096 * 1024; idx += GS) {
        int row = idx >> 10, k = idx & 1023;
        float w = (row < 3072) ? W_hh[row * 1024 + k] : lin_W[(row - 3072) * 1024 + k];
        bsplit(w, g_W0h[idx], g_W0l[idx]);
    }
    // phase B/C weights (K=2048), gate-split n
    for (int idx = gt; idx < 2 * 4096 * 2048; idx += GS) {
        int ll  = idx >> 23;
        int r   = idx & 8388607;
        int row = r >> 11, k = r & 2047;
        int qq  = row >> 10, jj = row & 1023;
        int lay = ll + 1;
        float w = 0.0f;
        if (qq < 2) {
            w = (k < 1024) ? W_ih[(size_t)(lay * 3072 + qq * 1024 + jj) * 1024 + k]
                           : W_hh[(size_t)(lay * 3072 + qq * 1024 + jj) * 1024 + (k - 1024)];
        } else if (qq == 2) {
            if (k < 1024) w = W_ih[(size_t)(lay * 3072 + 2048 + jj) * 1024 + k];
        } else {
            if (k >= 1024) w = W_hh[(size_t)(lay * 3072 + 2048 + jj) * 1024 + (k - 1024)];
        }
        bsplit(w, g_W12h[idx], g_W12l[idx]);
    }
    // fp32 token table: T[v][row] = embed[v].W_ih0[row] + b_ih0[row]  (warp shares row)
    for (int idx = gt; idx < 3072 * 128; idx += GS) {
        int row = idx >> 7, v = idx & 127;
        if (v < NV) {
            const float* e = embed + (size_t)v * 1024;
            const float* w = W_ih + (size_t)row * 1024;
            float a0 = 0, a1 = 0, a2 = 0, a3 = 0;
            for (int k = 0; k < 1024; k += 4) {
                a0 += e[k] * w[k];     a1 += e[k + 1] * w[k + 1];
                a2 += e[k + 2] * w[k + 2]; a3 += e[k + 3] * w[k + 3];
            }
            g_T[v * G3 + row] = (a0 + a1) + (a2 + a3) + b_ih[row];
        }
    }
    // state init (fp32 + bf16 hi/lo into parity-0 buffers)
    for (int idx = gt; idx < 3 * 64 * 1024; idx += GS) {
        int l = idx >> 16, r = idx & 65535, b = r >> 10, j = r & 1023;
        float v = init_state[l * 1024 + j];
        g_stf[idx] = v;
        __nv_bfloat16 h, lo;
        bsplit(v, h, lo);
        int c = (l == 0) ? j : (1024 + j);
        int d = AIDX(l, 0, b, c);
        g_Ahi[d] = h; g_Alo[d] = lo;
    }
    gridbar();

    // ================= STEP LOOP =================
    for (int u = 0; u < NSTEPS; ++u) {
        const int par = u & 1;

        // ----- phase A: layer0 h-GEMM (q=0..2) + output linear of u-1 (q=3), K=1024 -----
        {
            const __nv_bfloat16 *Ah, *Al;
            if (q < 3) { Ah = g_Ahi + AIDX(0, par, m0, 0);    Al = g_Alo + AIDX(0, par, m0, 0); }
            else       { Ah = g_Ahi + AIDX(2, par, m0, 1024); Al = g_Alo + AIDX(2, par, m0, 1024); }
            const int n0 = q * 1024 + cta * 8;
            float dhh[4] = {0, 0, 0, 0}, dhl[4] = {0, 0, 0, 0}, dlh[4] = {0, 0, 0, 0};
            run_gemm(Ah, Al, g_W0h + (size_t)n0 * 1024, g_W0l + (size_t)n0 * 1024,
                     1024, 64, lane, dhh, dhl, dlh);
            int rr = lane >> 2, cc = (lane & 3) << 1;
            sD[mw][q][rr][cc]         = dhh[0] + (dhl[0] + dlh[0]);
            sD[mw][q][rr][cc + 1]     = dhh[1] + (dhl[1] + dlh[1]);
            sD[mw][q][rr + 8][cc]     = dhh[2] + (dhl[2] + dlh[2]);
            sD[mw][q][rr + 8][cc + 1] = dhh[3] + (dhl[3] + dlh[3]);
        }
        __syncthreads();
        {   // epilogue A: GRU layer0 + out[u-1]
            int b = tid >> 3, jj = tid & 7, mm = b >> 4, rr = b & 15;
            float Dr = sD[mm][0][rr][jj], Dz = sD[mm][1][rr][jj];
            float Dn = sD[mm][2][rr][jj], Do = sD[mm][3][rr][jj];
            int jcol = cta * 8 + jj;
            int tok = (u == 0) ? (NV - 1) : y[b * UMX + (u - 1)];
            const float* Tv = g_T + (size_t)tok * G3;
            float r = sigm(Tv[jcol] + Dr + b_hh[jcol]);
            float z = sigm(Tv[1024 + jcol] + Dz + b_hh[1024 + jcol]);
            float n = tanhf(Tv[2048 + jcol] + r * (Dn + b_hh[2048 + jcol]));
            float hp = g_stf[b * 1024 + jcol];
            float h = (1.0f - z) * n + z * hp;
            g_stf[b * 1024 + jcol] = h;
            __nv_bfloat16 bh, bl;
            bsplit(h, bh, bl);
            int dx = AIDX(1, par, b, jcol);         // x for layer1 this step
            g_Ahi[dx] = bh; g_Alo[dx] = bl;
            int dh = AIDX(0, par ^ 1, b, jcol);     // h0 for next step
            g_Ahi[dh] = bh; g_Alo[dh] = bl;
            if (u > 0)
                out[(size_t)b * NSTEPS * 1024 + (size_t)(u - 1) * 1024 + jcol] = Do + lin_b[jcol];
        }
        gridbar();

        // ----- phases B, C: layers 1, 2 -----
#pragma unroll 1
        for (int l = 1; l <= 2; ++l) {
            {
                int kb, tiles;
                if (q < 2)       { kb = 0;    tiles = 128; }
                else if (q == 2) { kb = 0;    tiles = 64;  }
                else             { kb = 1024; tiles = 64;  }
                const __nv_bfloat16* Ah = g_Ahi + AIDX(l, par, m0, kb);
                const __nv_bfloat16* Al = g_Alo + AIDX(l, par, m0, kb);
                const size_t wof = ((size_t)(l - 1) * 4096 + q * 1024 + cta * 8) * 2048 + kb;
                float dhh[4] = {0, 0, 0, 0}, dhl[4] = {0, 0, 0, 0}, dlh[4] = {0, 0, 0, 0};
                run_gemm(Ah, Al, g_W12h + wof, g_W12l + wof, 2048, tiles, lane, dhh, dhl, dlh);
                int rr = lane >> 2, cc = (lane & 3) << 1;
                sD[mw][q][rr][cc]         = dhh[0] + (dhl[0] + dlh[0]);
                sD[mw][q][rr][cc + 1]     = dhh[1] + (dhl[1] + dlh[1]);
                sD[mw][q][rr + 8][cc]     = dhh[2] + (dhl[2] + dlh[2]);
                sD[mw][q][rr + 8][cc + 1] = dhh[3] + (dhl[3] + dlh[3]);
            }
            __syncthreads();
            {   // epilogue: GRU layer l
                int b = tid >> 3, jj = tid & 7, mm = b >> 4, rr = b & 15;
                float Gr = sD[mm][0][rr][jj], Gz = sD[mm][1][rr][jj];
                float Gi = sD[mm][2][rr][jj], Gh = sD[mm][3][rr][jj];
                int jcol = cta * 8 + jj;
                const float* bi = b_ih + l * G3;
                const float* bhv = b_hh + l * G3;
                float r = sigm(Gr + bi[jcol] + bhv[jcol]);
                float z = sigm(Gz + bi[1024 + jcol] + bhv[1024 + jcol]);
                float n = tanhf(Gi + bi[2048 + jcol] + r * (Gh + bhv[2048 + jcol]));
                float hp = g_stf[(l * 64 + b) * 1024 + jcol];
                float h = (1.0f - z) * n + z * hp;
                g_stf[(l * 64 + b) * 1024 + jcol] = h;
                __nv_bfloat16 bh16, bl16;
                bsplit(h, bh16, bl16);
                if (l == 1) {
                    int dx = AIDX(2, par, b, jcol);          // x for layer2 this step
                    g_Ahi[dx] = bh16; g_Alo[dx] = bl16;
                    int dh = AIDX(1, par ^ 1, b, 1024 + jcol);
                    g_Ahi[dh] = bh16; g_Alo[dh] = bl16;
                } else {
                    int dh = AIDX(2, par ^ 1, b, 1024 + jcol); // h2: lin + layer2 next step
                    g_Ahi[dh] = bh16; g_Alo[dh] = bl16;
                }
            }
            gridbar();
        }
    }

    // ================= FINAL OUTPUT (u = NSTEPS-1) =================
    {
        if (q == 3) {
            const int fpar = NSTEPS & 1;   // h2[256] parity
            const __nv_bfloat16* Ah = g_Ahi + AIDX(2, fpar, m0, 1024);
            const __nv_bfloat16* Al = g_Alo + AIDX(2, fpar, m0, 1024);
            const size_t wof = (size_t)(3072 + cta * 8) * 1024;
            float dhh[4] = {0, 0, 0, 0}, dhl[4] = {0, 0, 0, 0}, dlh[4] = {0, 0, 0, 0};
            run_gemm(Ah, Al, g_W0h + wof, g_W0l + wof, 1024, 64, lane, dhh, dhl, dlh);
            int rr = lane >> 2, cc = (lane & 3) << 1;
            sD[mw][3][rr][cc]         = dhh[0] + (dhl[0] + dlh[0]);
            sD[mw][3][rr][cc + 1]     = dhh[1] + (dhl[1] + dlh[1]);
            sD[mw][3][rr + 8][cc]     = dhh[2] + (dhl[2] + dlh[2]);
            sD[mw][3][rr + 8][cc + 1] = dhh[3] + (dhl[3] + dlh[3]);
        }
        __syncthreads();
        int b = tid >> 3, jj = tid & 7;
        int jcol = cta * 8 + jj;
        out[(size_t)b * NSTEPS * 1024 + (size_t)(NSTEPS - 1) * 1024 + jcol] =
            sD[b >> 4][3][b & 15][jj] + lin_b[jcol];
    }
}

extern "C" void kernel_launch(void* const* d_in, const int* in_sizes, int n_in,
                              void* d_out, int out_size) {
    (void)in_sizes; (void)n_in; (void)out_size;
    const int*   y          = (const int*)  d_in[0];
    // d_in[1] = U (unused by the reference math)
    const float* embed      = (const float*)d_in[2];
    const float* W_ih       = (const float*)d_in[3];
    const float* W_hh       = (const float*)d_in[4];
    const float* b_ih       = (const float*)d_in[5];
    const float* b_hh       = (const float*)d_in[6];
    const float* init_state = (const float*)d_in[7];
    const float* lin_W      = (const float*)d_in[8];
    const float* lin_b      = (const float*)d_in[9];
    float* out = (float*)d_out;

    decoder_kernel<<<NCTA, NTHR>>>(y, embed, W_ih, W_hh, b_ih, b_hh,
                                   init_state, lin_W, lin_b, out);
}

// round 7
// speedup vs baseline: 4.3660x; 3.9548x over previous
#include <cuda_runtime.h>
#include <cuda_bf16.h>

#define NV     101          // tokens incl. start symbol (start = 100)
#define UMX    256
#define NSTEPS 257
#define G3     3072
#define NCTA   128
#define NTHR   512

typedef unsigned u32;

// ---------------- static device scratch (no runtime allocation) ----------------
// Fragment-packed weights.
// g_W0p: phase A (K=1024): n-rows 0..3071 = W_hh layer0 (r,z,n), 3072..4095 = lin_W.
//   [ntile(512)][ktile(64)][lane(32)] : uint4 = {Bhi.r0, Bhi.r1, Blo.r0, Blo.r1}
__device__ __align__(16) uint4 g_W0p[512 * 64 * 32];            // 16 MB
// g_W12p: layers 1,2 (K=2048): per layer n-row q*1024+j:
//   q=0:[Wih_r|Whh_r] q=1:[Wih_z|Whh_z] q=2:[Wih_n|0] q=3:[0|Whh_n]
//   [layer(2)][ntile(512)][ktile(128)][lane(32)]
__device__ __align__(16) uint4 g_W12p[2 * 512 * 128 * 32];      // 64 MB
// Fragment-packed activations: [l(3)][par(2)][mtile(4)][ktile(128)][plane(2)][lane(32)]
//   l=0: cols 0..1023 = h0; l=1,2: cols 0..1023 = x, 1024..2047 = h_prev
__device__ __align__(16) uint4 g_A[3 * 2 * 4 * 128 * 2 * 32];   // 3 MB
__device__ float g_T[NV * G3];          // layer0 gi table (incl b_ih0), fp32
__device__ float g_stf[3 * 64 * 1024];  // fp32 states [l][b][j]
__device__ unsigned g_bar;

// ---------------- grid barrier (128 CTAs, 1/SM, co-resident) ----------------
__device__ __forceinline__ void gridbar() {
    __threadfence();
    __syncthreads();
    if (threadIdx.x == 0) {
        unsigned ticket = atomicAdd(&g_bar, 1u) + 1u;
        unsigned target = ((ticket + NCTA - 1u) / NCTA) * NCTA;
        while (*((volatile unsigned*)&g_bar) < target) { __nanosleep(32); }
    }
    __syncthreads();
    __threadfence();
}

__device__ __forceinline__ float sigm(float t) { return 1.0f / (1.0f + expf(-t)); }

// split fp32 -> (hi, lo) bf16 bit patterns
__device__ __forceinline__ void sp(float w, u32& hb, u32& lb) {
    __nv_bfloat16 h = __float2bfloat16(w);
    hb = (u32)__bfloat16_as_ushort(h);
    lb = (u32)__bfloat16_as_ushort(__float2bfloat16(w - __bfloat162float(h)));
}
// pack 4 weights (b0 pair = a,b ; b1 pair = c,d) into fragment uint4
__device__ __forceinline__ uint4 pack4(float a, float b, float c, float d) {
    u32 ah, al, bh, bl, ch, cl, dh, dl;
    sp(a, ah, al); sp(b, bh, bl); sp(c, ch, cl); sp(d, dh, dl);
    uint4 v;
    v.x = ah | (bh << 16);   // hi b0
    v.y = ch | (dh << 16);   // hi b1
    v.z = al | (bl << 16);   // lo b0
    v.w = cl | (dl << 16);   // lo b1
    return v;
}

// A-buffer offset (uint4 units, excluding lane): plane0 base of (l,par,mtile,ktile)
__device__ __forceinline__ size_t aoff(int l, int par, int mt, int kt) {
    return (size_t)((((l * 2 + par) * 4 + mt) * 128 + kt) * 2) * 32;
}

// Write activation element (b, c) as hi/lo bf16 into fragment layout
__device__ __forceinline__ void storeA(int l, int par, int b, int c, float v) {
    int mt = b >> 4, mr = b & 15, kt = c >> 4, kk = c & 15;
    int lane = (mr & 7) * 4 + ((kk & 7) >> 1);
    int slot = (mr >> 3) + ((kk >> 3) << 1);
    u32 hb, lb;
    sp(v, hb, lb);
    __nv_bfloat16* p = (__nv_bfloat16*)(g_A + aoff(l, par, mt, kt) + lane);
    int e = slot * 2 + (kk & 1);
    p[e] = __ushort_as_bfloat16((unsigned short)hb);
    p[e + 256] = __ushort_as_bfloat16((unsigned short)lb);   // plane1 = +32 uint4
}

// ---------------- mma.m16n8k16 bf16 ----------------
__device__ __forceinline__ void mma_bf16(float* d, const uint4& a, u32 b0, u32 b1) {
    asm volatile(
        "mma.sync.aligned.m16n8k16.row.col.f32.bf16.bf16.f32 "
        "{%0,%1,%2,%3}, {%4,%5,%6,%7}, {%8,%9}, {%0,%1,%2,%3};"
        : "+f"(d[0]), "+f"(d[1]), "+f"(d[2]), "+f"(d[3])
        : "r"(a.x), "r"(a.y), "r"(a.z), "r"(a.w), "r"(b0), "r"(b1));
}

// K-loop over fragment-packed tiles. A stride 64 uint4/tile (hi @+0, lo @+32); B stride 32.
__device__ __forceinline__ void run_gemm(const uint4* __restrict__ A,
                                         const uint4* __restrict__ B,
                                         int tiles, float* dhh, float* dhl, float* dlh)
{
    uint4 ah0 = A[0], al0 = A[32], b0 = B[0];
#pragma unroll 1
    for (int t = 0; t + 2 < tiles; t += 2) {
        uint4 ah1 = A[(t + 1) * 64], al1 = A[(t + 1) * 64 + 32], b1 = B[(t + 1) * 32];
        mma_bf16(dhh, ah0, b0.x, b0.y);
        mma_bf16(dhl, ah0, b0.z, b0.w);
        mma_bf16(dlh, al0, b0.x, b0.y);
        ah0 = A[(t + 2) * 64]; al0 = A[(t + 2) * 64 + 32]; b0 = B[(t + 2) * 32];
        mma_bf16(dhh, ah1, b1.x, b1.y);
        mma_bf16(dhl, ah1, b1.z, b1.w);
        mma_bf16(dlh, al1, b1.x, b1.y);
    }
    uint4 ah1 = A[(tiles - 1) * 64], al1 = A[(tiles - 1) * 64 + 32], b1 = B[(tiles - 1) * 32];
    mma_bf16(dhh, ah0, b0.x, b0.y);
    mma_bf16(dhl, ah0, b0.z, b0.w);
    mma_bf16(dlh, al0, b0.x, b0.y);
    mma_bf16(dhh, ah1, b1.x, b1.y);
    mma_bf16(dhl, ah1, b1.z, b1.w);
    mma_bf16(dlh, al1, b1.x, b1.y);
}

// ================================================================================
__global__ void __launch_bounds__(NTHR, 1)
decoder_kernel(const int*   __restrict__ y,
               const float* __restrict__ embed,
               const float* __restrict__ W_ih,
               const float* __restrict__ W_hh,
               const float* __restrict__ b_ih,
               const float* __restrict__ b_hh,
               const float* __restrict__ init_state,
               const float* __restrict__ lin_W,
               const float* __restrict__ lin_b,
               float*       __restrict__ out)
{
    const int tid  = threadIdx.x;
    const int lane = tid & 31;
    const int wid  = tid >> 5;          // 0..15
    const int mw   = wid & 3;           // m-tile (16 batches)
    const int q    = wid >> 2;          // n-group: 0=r 1=z 2=i_n 3=h_n (phase A: 3=lin)
    const int cta  = blockIdx.x;
    const int gt   = cta * NTHR + tid;
    const int GS   = NCTA * NTHR;

    __shared__ float sD[4][4][16][8];   // [mtile][q][row][col] 8 KB

    // ================= PROLOGUE =================
    // pack phase-A weights (W_hh layer0 + lin_W), K=1024
    for (int idx = gt; idx < 512 * 64 * 32; idx += GS) {
        int ln = idx & 31, t = (idx >> 5) & 63, NT = idx >> 11;
        int n  = NT * 8 + (ln >> 2);
        int k0 = t * 16 + ((ln & 3) << 1);
        const float* src = (n < 3072) ? (W_hh + (size_t)n * 1024)
                                      : (lin_W + (size_t)(n - 3072) * 1024);
        g_W0p[idx] = pack4(src[k0], src[k0 + 1], src[k0 + 8], src[k0 + 9]);
    }
    // pack layer1/2 weights (gate-split), K=2048
    for (int idx = gt; idx < 2 * 512 * 128 * 32; idx += GS) {
        int ln = idx & 31, t = (idx >> 5) & 127, NT = (idx >> 12) & 511, ll = idx >> 21;
        int n  = NT * 8 + (ln >> 2);
        int qq = n >> 10, jj = n & 1023;
        int k0 = t * 16 + ((ln & 3) << 1);
        int lay = ll + 1;
        float w[4];
#pragma unroll
        for (int i = 0; i < 4; ++i) {
            int k = k0 + ((i >> 1) << 3) + (i & 1);   // k0, k0+1, k0+8, k0+9
            float v = 0.0f;
            if (qq < 2) {
                v = (k < 1024) ? W_ih[((size_t)lay * 3072 + qq * 1024 + jj) * 1024 + k]
                               : W_hh[((size_t)lay * 3072 + qq * 1024 + jj) * 1024 + k - 1024];
            } else if (qq == 2) {
                if (k < 1024) v = W_ih[((size_t)lay * 3072 + 2048 + jj) * 1024 + k];
            } else {
                if (k >= 1024) v = W_hh[((size_t)lay * 3072 + 2048 + jj) * 1024 + k - 1024];
            }
            w[i] = v;
        }
        g_W12p[idx] = pack4(w[0], w[1], w[2], w[3]);
    }
    // fp32 token table: T[v][row] = embed[v] . W_ih0[row] + b_ih0[row]
    for (int idx = gt; idx < 3072 * 128; idx += GS) {
        int row = idx >> 7, v = idx & 127;
        if (v < NV) {
            const float* e = embed + (size_t)v * 1024;
            const float* w = W_ih + (size_t)row * 1024;
            float a0 = 0, a1 = 0, a2 = 0, a3 = 0;
            for (int k = 0; k < 1024; k += 4) {
                a0 += e[k] * w[k];         a1 += e[k + 1] * w[k + 1];
                a2 += e[k + 2] * w[k + 2]; a3 += e[k + 3] * w[k + 3];
            }
            g_T[v * G3 + row] = (a0 + a1) + (a2 + a3) + b_ih[row];
        }
    }
    // state init: fp32 + fragment-packed bf16 (parity 0)
    for (int idx = gt; idx < 3 * 64 * 1024; idx += GS) {
        int l = idx >> 16, r = idx & 65535, b = r >> 10, j = r & 1023;
        float v = init_state[l * 1024 + j];
        g_stf[idx] = v;
        storeA(l, 0, b, (l == 0) ? j : (1024 + j), v);
    }
    gridbar();

    // ================= STEP LOOP =================
    for (int u = 0; u < NSTEPS; ++u) {
        const int par = u & 1;

        // ----- phase A: layer0 h-GEMM (q=0..2) + output linear of u-1 (q=3), K=1024 -----
        {
            const uint4* A = g_A + ((q < 3) ? aoff(0, par, mw, 0) : aoff(2, par, mw, 64)) + lane;
            const uint4* B = g_W0p + (size_t)(q * 128 + cta) * 64 * 32 + lane;
            float dhh[4] = {0, 0, 0, 0}, dhl[4] = {0, 0, 0, 0}, dlh[4] = {0, 0, 0, 0};
            run_gemm(A, B, 64, dhh, dhl, dlh);
            int rr = lane >> 2, cc = (lane & 3) << 1;
            sD[mw][q][rr][cc]         = dhh[0] + (dhl[0] + dlh[0]);
            sD[mw][q][rr][cc + 1]     = dhh[1] + (dhl[1] + dlh[1]);
            sD[mw][q][rr + 8][cc]     = dhh[2] + (dhl[2] + dlh[2]);
            sD[mw][q][rr + 8][cc + 1] = dhh[3] + (dhl[3] + dlh[3]);
        }
        __syncthreads();
        {   // epilogue A: GRU layer0 + out[u-1]
            int b = tid >> 3, jj = tid & 7, mm = b >> 4, rr = b & 15;
            float Dr = sD[mm][0][rr][jj], Dz = sD[mm][1][rr][jj];
            float Dn = sD[mm][2][rr][jj], Do = sD[mm][3][rr][jj];
            int jcol = cta * 8 + jj;
            int tok = (u == 0) ? (NV - 1) : y[b * UMX + (u - 1)];
            const float* Tv = g_T + (size_t)tok * G3;
            float r = sigm(Tv[jcol] + Dr + b_hh[jcol]);
            float z = sigm(Tv[1024 + jcol] + Dz + b_hh[1024 + jcol]);
            float n = tanhf(Tv[2048 + jcol] + r * (Dn + b_hh[2048 + jcol]));
            float hp = g_stf[b * 1024 + jcol];
            float h = (1.0f - z) * n + z * hp;
            g_stf[b * 1024 + jcol] = h;
            storeA(1, par, b, jcol, h);          // x for layer1 this step
            storeA(0, par ^ 1, b, jcol, h);      // h0 for next step
            if (u > 0)
                out[(size_t)b * NSTEPS * 1024 + (size_t)(u - 1) * 1024 + jcol] = Do + lin_b[jcol];
        }
        gridbar();

        // ----- phases B, C: layers 1, 2 -----
#pragma unroll 1
        for (int l = 1; l <= 2; ++l) {
            {
                int kbt   = (q == 3) ? 64 : 0;
                int tiles = (q < 2) ? 128 : 64;
                const uint4* A = g_A + aoff(l, par, mw, kbt) + lane;
                const uint4* B = g_W12p +
                    ((size_t)((l - 1) * 512 + q * 128 + cta) * 128 + kbt) * 32 + lane;
                float dhh[4] = {0, 0, 0, 0}, dhl[4] = {0, 0, 0, 0}, dlh[4] = {0, 0, 0, 0};
                run_gemm(A, B, tiles, dhh, dhl, dlh);
                int rr = lane >> 2, cc = (lane & 3) << 1;
                sD[mw][q][rr][cc]         = dhh[0] + (dhl[0] + dlh[0]);
                sD[mw][q][rr][cc + 1]     = dhh[1] + (dhl[1] + dlh[1]);
                sD[mw][q][rr + 8][cc]     = dhh[2] + (dhl[2] + dlh[2]);
                sD[mw][q][rr + 8][cc + 1] = dhh[3] + (dhl[3] + dlh[3]);
            }
            __syncthreads();
            {   // epilogue: GRU layer l
                int b = tid >> 3, jj = tid & 7, mm = b >> 4, rr = b & 15;
                float Gr = sD[mm][0][rr][jj], Gz = sD[mm][1][rr][jj];
                float Gi = sD[mm][2][rr][jj], Gh = sD[mm][3][rr][jj];
                int jcol = cta * 8 + jj;
                const float* bi  = b_ih + l * G3;
                const float* bhv = b_hh + l * G3;
                float r = sigm(Gr + bi[jcol] + bhv[jcol]);
                float z = sigm(Gz + bi[1024 + jcol] + bhv[1024 + jcol]);
                float n = tanhf(Gi + bi[2048 + jcol] + r * (Gh + bhv[2048 + jcol]));
                float hp = g_stf[(l * 64 + b) * 1024 + jcol];
                float h = (1.0f - z) * n + z * hp;
                g_stf[(l * 64 + b) * 1024 + jcol] = h;
                if (l == 1) {
                    storeA(2, par, b, jcol, h);              // x for layer2 this step
                    storeA(1, par ^ 1, b, 1024 + jcol, h);   // h1 next step
                } else {
                    storeA(2, par ^ 1, b, 1024 + jcol, h);   // h2: lin + layer2 next step
                }
            }
            gridbar();
        }
    }

    // ================= FINAL OUTPUT (u = NSTEPS-1) =================
    {
        if (q == 3) {
            const uint4* A = g_A + aoff(2, NSTEPS & 1, mw, 64) + lane;
            const uint4* B = g_W0p + (size_t)(384 + cta) * 64 * 32 + lane;
            float dhh[4] = {0, 0, 0, 0}, dhl[4] = {0, 0, 0, 0}, dlh[4] = {0, 0, 0, 0};
            run_gemm(A, B, 64, dhh, dhl, dlh);
            int rr = lane >> 2, cc = (lane & 3) << 1;
            sD[mw][3][rr][cc]         = dhh[0] + (dhl[0] + dlh[0]);
            sD[mw][3][rr][cc + 1]     = dhh[1] + (dhl[1] + dlh[1]);
            sD[mw][3][rr + 8][cc]     = dhh[2] + (dhl[2] + dlh[2]);
            sD[mw][3][rr + 8][cc + 1] = dhh[3] + (dhl[3] + dlh[3]);
        }
        __syncthreads();
        int b = tid >> 3, jj = tid & 7;
        int jcol = cta * 8 + jj;
        out[(size_t)b * NSTEPS * 1024 + (size_t)(NSTEPS - 1) * 1024 + jcol] =
            sD[b >> 4][3][b & 15][jj] + lin_b[jcol];
    }
}

extern "C" void kernel_launch(void* const* d_in, const int* in_sizes, int n_in,
                              void* d_out, int out_size) {
    (void)in_sizes; (void)n_in; (void)out_size;
    const int*   y          = (const int*)  d_in[0];
    // d_in[1] = U (unused by the reference math)
    const float* embed      = (const float*)d_in[2];
    const float* W_ih       = (const float*)d_in[3];
    const float* W_hh       = (const float*)d_in[4];
    const float* b_ih       = (const float*)d_in[5];
    const float* b_hh       = (const float*)d_in[6];
    const float* init_state = (const float*)d_in[7];
    const float* lin_W      = (const float*)d_in[8];
    const float* lin_b      = (const float*)d_in[9];
    float* out = (float*)d_out;

    decoder_kernel<<<NCTA, NTHR>>>(y, embed, W_ih, W_hh, b_ih, b_hh,
                                   init_state, lin_W, lin_b, out);
}

// round 8
// speedup vs baseline: 6.8310x; 1.5646x over previous
#include <cuda_runtime.h>
#include <cuda_bf16.h>

#define NV     101          // tokens incl. start symbol (start = 100)
#define UMX    256
#define NSTEPS 257
#define G3     3072
#define NCTA   128
#define NTHR   512

typedef unsigned u32;

// ---------------- static device scratch (no runtime allocation) ----------------
// Fragment-packed weights.
// g_W0p: phase A (K=1024): n-rows 0..3071 = W_hh layer0 (r,z,n), 3072..4095 = lin_W.
//   [ntile(512)][ktile(64)][lane(32)] : uint4 = {Bhi.r0, Bhi.r1, Blo.r0, Blo.r1}
__device__ __align__(16) uint4 g_W0p[512 * 64 * 32];            // 16 MB
// g_W12p: layers 1,2 (K=2048): per layer n-row q*1024+j:
//   q=0:[Wih_r|Whh_r] q=1:[Wih_z|Whh_z] q=2:[Wih_n|0] q=3:[0|Whh_n]
//   [layer(2)][ntile(512)][ktile(128)][lane(32)]
__device__ __align__(16) uint4 g_W12p[2 * 512 * 128 * 32];      // 64 MB
// Fragment-packed activations: [l(3)][par(2)][mtile(4)][ktile(128)][plane(2)][lane(32)]
//   l=0: cols 0..1023 = h0; l=1,2: cols 0..1023 = x, 1024..2047 = h_prev
__device__ __align__(16) uint4 g_A[3 * 2 * 4 * 128 * 2 * 32];   // 3 MB
__device__ float g_T[NV * G3];          // layer0 gi table (incl b_ih0), fp32
__device__ float g_stf[3 * 64 * 1024];  // fp32 states [l][b][j]
__device__ unsigned g_bar;

// ---------------- grid barrier (128 CTAs, 1/SM, co-resident) ----------------
__device__ __forceinline__ void gridbar() {
    __threadfence();
    __syncthreads();
    if (threadIdx.x == 0) {
        unsigned ticket = atomicAdd(&g_bar, 1u) + 1u;
        unsigned target = ((ticket + NCTA - 1u) / NCTA) * NCTA;
        while (*((volatile unsigned*)&g_bar) < target) { __nanosleep(32); }
    }
    __syncthreads();
    __threadfence();
}

__device__ __forceinline__ float sigm(float t) { return 1.0f / (1.0f + expf(-t)); }

// split fp32 -> (hi, lo) bf16 bit patterns
__device__ __forceinline__ void sp(float w, u32& hb, u32& lb) {
    __nv_bfloat16 h = __float2bfloat16(w);
    hb = (u32)__bfloat16_as_ushort(h);
    lb = (u32)__bfloat16_as_ushort(__float2bfloat16(w - __bfloat162float(h)));
}
__device__ __forceinline__ uint4 pack4(float a, float b, float c, float d) {
    u32 ah, al, bh, bl, ch, cl, dh, dl;
    sp(a, ah, al); sp(b, bh, bl); sp(c, ch, cl); sp(d, dh, dl);
    uint4 v;
    v.x = ah | (bh << 16);   // hi b0
    v.y = ch | (dh << 16);   // hi b1
    v.z = al | (bl << 16);   // lo b0
    v.w = cl | (dl << 16);   // lo b1
    return v;
}

// A-buffer offset (uint4 units, excluding lane): plane0 base of (l,par,mtile,ktile)
__device__ __forceinline__ size_t aoff(int l, int par, int mt, int kt) {
    return (size_t)((((l * 2 + par) * 4 + mt) * 128 + kt) * 2) * 32;
}

// Write activation element (b, c) as hi/lo bf16 into fragment layout
__device__ __forceinline__ void storeA(int l, int par, int b, int c, float v) {
    int mt = b >> 4, mr = b & 15, kt = c >> 4, kk = c & 15;
    int lane = (mr & 7) * 4 + ((kk & 7) >> 1);
    int slot = (mr >> 3) + ((kk >> 3) << 1);
    u32 hb, lb;
    sp(v, hb, lb);
    __nv_bfloat16* p = (__nv_bfloat16*)(g_A + aoff(l, par, mt, kt) + lane);
    int e = slot * 2 + (kk & 1);
    p[e] = __ushort_as_bfloat16((unsigned short)hb);
    p[e + 256] = __ushort_as_bfloat16((unsigned short)lb);   // plane1 = +32 uint4
}

// ---------------- mma.m16n8k16 bf16 ----------------
__device__ __forceinline__ void mma_bf16(float* d, const uint4& a, u32 b0, u32 b1) {
    asm volatile(
        "mma.sync.aligned.m16n8k16.row.col.f32.bf16.bf16.f32 "
        "{%0,%1,%2,%3}, {%4,%5,%6,%7}, {%8,%9}, {%0,%1,%2,%3};"
        : "+f"(d[0]), "+f"(d[1]), "+f"(d[2]), "+f"(d[3])
        : "r"(a.x), "r"(a.y), "r"(a.z), "r"(a.w), "r"(b0), "r"(b1));
}
// 3-chain triple for one gate (hi*hi, hi*lo, lo*hi)
__device__ __forceinline__ void mma3(float d[3][4], const uint4& ah, const uint4& al,
                                     const uint4& b) {
    mma_bf16(d[0], ah, b.x, b.y);
    mma_bf16(d[1], ah, b.z, b.w);
    mma_bf16(d[2], al, b.x, b.y);
}
// combine 3 chains and store a 16x8 tile into smem slab (float[128])
__device__ __forceinline__ void stD(float* base, int rr, int cc, const float d[3][4]) {
    base[rr * 8 + cc]           = d[0][0] + (d[1][0] + d[2][0]);
    base[rr * 8 + cc + 1]       = d[0][1] + (d[1][1] + d[2][1]);
    base[(rr + 8) * 8 + cc]     = d[0][2] + (d[1][2] + d[2][2]);
    base[(rr + 8) * 8 + cc + 1] = d[0][3] + (d[1][3] + d[2][3]);
}
__device__ __forceinline__ void stZ(float* base, int rr, int cc) {
    base[rr * 8 + cc] = 0.0f;           base[rr * 8 + cc + 1] = 0.0f;
    base[(rr + 8) * 8 + cc] = 0.0f;     base[(rr + 8) * 8 + cc + 1] = 0.0f;
}

// ================================================================================
__global__ void __launch_bounds__(NTHR, 1)
decoder_kernel(const int*   __restrict__ y,
               const float* __restrict__ embed,
               const float* __restrict__ W_ih,
               const float* __restrict__ W_hh,
               const float* __restrict__ b_ih,
               const float* __restrict__ b_hh,
               const float* __restrict__ init_state,
               const float* __restrict__ lin_W,
               const float* __restrict__ lin_b,
               float*       __restrict__ out)
{
    const int tid  = threadIdx.x;
    const int lane = tid & 31;
    const int wid  = tid >> 5;          // 0..15
    const int mw   = wid & 3;           // m-tile (16 batches)
    const int ks   = wid >> 2;          // k-slice 0..3
    const int cta  = blockIdx.x;
    const int gt   = cta * NTHR + tid;
    const int GS   = NCTA * NTHR;
    const int rr   = lane >> 2, cc = (lane & 3) << 1;

    __shared__ float sD[4][4][4][128];  // [ks][mtile][q] 16x8 tile, 32 KB

    // ================= PROLOGUE =================
    for (int idx = gt; idx < 512 * 64 * 32; idx += GS) {
        int ln = idx & 31, t = (idx >> 5) & 63, NT = idx >> 11;
        int n  = NT * 8 + (ln >> 2);
        int k0 = t * 16 + ((ln & 3) << 1);
        const float* src = (n < 3072) ? (W_hh + (size_t)n * 1024)
                                      : (lin_W + (size_t)(n - 3072) * 1024);
        g_W0p[idx] = pack4(src[k0], src[k0 + 1], src[k0 + 8], src[k0 + 9]);
    }
    for (int idx = gt; idx < 2 * 512 * 128 * 32; idx += GS) {
        int ln = idx & 31, t = (idx >> 5) & 127, NT = (idx >> 12) & 511, ll = idx >> 21;
        int n  = NT * 8 + (ln >> 2);
        int qq = n >> 10, jj = n & 1023;
        int k0 = t * 16 + ((ln & 3) << 1);
        int lay = ll + 1;
        float w[4];
#pragma unroll
        for (int i = 0; i < 4; ++i) {
            int k = k0 + ((i >> 1) << 3) + (i & 1);   // k0, k0+1, k0+8, k0+9
            float v = 0.0f;
            if (qq < 2) {
                v = (k < 1024) ? W_ih[((size_t)lay * 3072 + qq * 1024 + jj) * 1024 + k]
                               : W_hh[((size_t)lay * 3072 + qq * 1024 + jj) * 1024 + k - 1024];
            } else if (qq == 2) {
                if (k < 1024) v = W_ih[((size_t)lay * 3072 + 2048 + jj) * 1024 + k];
            } else {
                if (k >= 1024) v = W_hh[((size_t)lay * 3072 + 2048 + jj) * 1024 + k - 1024];
            }
            w[i] = v;
        }
        g_W12p[idx] = pack4(w[0], w[1], w[2], w[3]);
    }
    // fp32 token table: T[v][row] = embed[v] . W_ih0[row] + b_ih0[row]
    for (int idx = gt; idx < 3072 * 128; idx += GS) {
        int row = idx >> 7, v = idx & 127;
        if (v < NV) {
            const float* e = embed + (size_t)v * 1024;
            const float* w = W_ih + (size_t)row * 1024;
            float a0 = 0, a1 = 0, a2 = 0, a3 = 0;
            for (int k = 0; k < 1024; k += 4) {
                a0 += e[k] * w[k];         a1 += e[k + 1] * w[k + 1];
                a2 += e[k + 2] * w[k + 2]; a3 += e[k + 3] * w[k + 3];
            }
            g_T[v * G3 + row] = (a0 + a1) + (a2 + a3) + b_ih[row];
        }
    }
    for (int idx = gt; idx < 3 * 64 * 1024; idx += GS) {
        int l = idx >> 16, r = idx & 65535, b = r >> 10, j = r & 1023;
        float v = init_state[l * 1024 + j];
        g_stf[idx] = v;
        storeA(l, 0, b, (l == 0) ? j : (1024 + j), v);
    }
    gridbar();

    // ================= STEP LOOP =================
    for (int u = 0; u < NSTEPS; ++u) {
        const int par = u & 1;

        // ----- phase A: layer0 h-GEMM (gates r,z,n on A=h0) + lin (on A=h2), K=1024 -----
        {
            const int t0 = ks * 16;
            const uint4* A0 = g_A + aoff(0, par, mw, t0) + lane;
            const uint4* A2 = g_A + aoff(2, par, mw, 64 + t0) + lane;
            const uint4* B0 = g_W0p + ((size_t)(0 * 128 + cta) * 64 + t0) * 32 + lane;
            const uint4* B1 = g_W0p + ((size_t)(1 * 128 + cta) * 64 + t0) * 32 + lane;
            const uint4* B2 = g_W0p + ((size_t)(2 * 128 + cta) * 64 + t0) * 32 + lane;
            const uint4* B3 = g_W0p + ((size_t)(3 * 128 + cta) * 64 + t0) * 32 + lane;
            float d0[3][4] = {}, d1[3][4] = {}, d2[3][4] = {}, d3[3][4] = {};
#pragma unroll 1
            for (int i = 0; i < 16; ++i) {
                uint4 ah = A0[i * 64], al = A0[i * 64 + 32];
                uint4 ch = A2[i * 64], cl = A2[i * 64 + 32];
                uint4 b0 = B0[i * 32], b1 = B1[i * 32], b2 = B2[i * 32], b3 = B3[i * 32];
                mma3(d0, ah, al, b0);
                mma3(d1, ah, al, b1);
                mma3(d2, ah, al, b2);
                mma3(d3, ch, cl, b3);
            }
            stD(sD[ks][mw][0], rr, cc, d0);
            stD(sD[ks][mw][1], rr, cc, d1);
            stD(sD[ks][mw][2], rr, cc, d2);
            stD(sD[ks][mw][3], rr, cc, d3);
        }
        __syncthreads();
        {   // epilogue A: GRU layer0 + out[u-1]
            int b = tid >> 3, jj = tid & 7, mm = b >> 4, r2 = b & 15;
            float Dr = 0, Dz = 0, Dn = 0, Do = 0;
#pragma unroll
            for (int s = 0; s < 4; ++s) {
                Dr += sD[s][mm][0][r2 * 8 + jj];
                Dz += sD[s][mm][1][r2 * 8 + jj];
                Dn += sD[s][mm][2][r2 * 8 + jj];
                Do += sD[s][mm][3][r2 * 8 + jj];
            }
            int jcol = cta * 8 + jj;
            int tok = (u == 0) ? (NV - 1) : y[b * UMX + (u - 1)];
            const float* Tv = g_T + (size_t)tok * G3;
            float r = sigm(Tv[jcol] + Dr + b_hh[jcol]);
            float z = sigm(Tv[1024 + jcol] + Dz + b_hh[1024 + jcol]);
            float n = tanhf(Tv[2048 + jcol] + r * (Dn + b_hh[2048 + jcol]));
            float hp = g_stf[b * 1024 + jcol];
            float h = (1.0f - z) * n + z * hp;
            g_stf[b * 1024 + jcol] = h;
            storeA(1, par, b, jcol, h);          // x for layer1 this step
            storeA(0, par ^ 1, b, jcol, h);      // h0 for next step
            if (u > 0)
                out[(size_t)b * NSTEPS * 1024 + (size_t)(u - 1) * 1024 + jcol] = Do + lin_b[jcol];
        }
        gridbar();

        // ----- phases B, C: layers 1, 2 (K=2048; gate n split by k-half) -----
#pragma unroll 1
        for (int l = 1; l <= 2; ++l) {
            {
                const int t0 = ks * 32;
                const int q23 = 2 + (ks >> 1);          // ks 0,1 -> i_n ; ks 2,3 -> h_n
                const uint4* A  = g_A + aoff(l, par, mw, t0) + lane;
                const uint4* B0 = g_W12p + ((size_t)((l - 1) * 512 + 0 * 128 + cta) * 128 + t0) * 32 + lane;
                const uint4* B1 = g_W12p + ((size_t)((l - 1) * 512 + 1 * 128 + cta) * 128 + t0) * 32 + lane;
                const uint4* B2 = g_W12p + ((size_t)((l - 1) * 512 + q23 * 128 + cta) * 128 + t0) * 32 + lane;
                float d0[3][4] = {}, d1[3][4] = {}, d2[3][4] = {};
#pragma unroll 2
                for (int i = 0; i < 32; ++i) {
                    uint4 ah = A[i * 64], al = A[i * 64 + 32];
                    uint4 b0 = B0[i * 32], b1 = B1[i * 32], b2 = B2[i * 32];
                    mma3(d0, ah, al, b0);
                    mma3(d1, ah, al, b1);
                    mma3(d2, ah, al, b2);
                }
                stD(sD[ks][mw][0], rr, cc, d0);
                stD(sD[ks][mw][1], rr, cc, d1);
                stD(sD[ks][mw][q23], rr, cc, d2);
                stZ(sD[ks][mw][5 - q23], rr, cc);
            }
            __syncthreads();
            {   // epilogue: GRU layer l
                int b = tid >> 3, jj = tid & 7, mm = b >> 4, r2 = b & 15;
                float Gr = 0, Gz = 0, Gi = 0, Gh = 0;
#pragma unroll
                for (int s = 0; s < 4; ++s) {
                    Gr += sD[s][mm][0][r2 * 8 + jj];
                    Gz += sD[s][mm][1][r2 * 8 + jj];
                    Gi += sD[s][mm][2][r2 * 8 + jj];
                    Gh += sD[s][mm][3][r2 * 8 + jj];
                }
                int jcol = cta * 8 + jj;
                const float* bi  = b_ih + l * G3;
                const float* bhv = b_hh + l * G3;
                float r = sigm(Gr + bi[jcol] + bhv[jcol]);
                float z = sigm(Gz + bi[1024 + jcol] + bhv[1024 + jcol]);
                float n = tanhf(Gi + bi[2048 + jcol] + r * (Gh + bhv[2048 + jcol]));
                float hp = g_stf[(l * 64 + b) * 1024 + jcol];
                float h = (1.0f - z) * n + z * hp;
                g_stf[(l * 64 + b) * 1024 + jcol] = h;
                if (l == 1) {
                    storeA(2, par, b, jcol, h);              // x for layer2 this step
                    storeA(1, par ^ 1, b, 1024 + jcol, h);   // h1 next step
                } else {
                    storeA(2, par ^ 1, b, 1024 + jcol, h);   // h2: lin + layer2 next step
                }
            }
            gridbar();
        }
    }

    // ================= FINAL OUTPUT (u = NSTEPS-1) =================
    {
        const int t0 = ks * 16;
        const uint4* A2 = g_A + aoff(2, NSTEPS & 1, mw, 64 + t0) + lane;
        const uint4* B3 = g_W0p + ((size_t)(384 + cta) * 64 + t0) * 32 + lane;
        float d[3][4] = {};
#pragma unroll 2
        for (int i = 0; i < 16; ++i) {
            uint4 ch = A2[i * 64], cl = A2[i * 64 + 32];
            uint4 b3 = B3[i * 32];
            mma3(d, ch, cl, b3);
        }
        stD(sD[ks][mw][0], rr, cc, d);
    }
    __syncthreads();
    {
        int b = tid >> 3, jj = tid & 7, mm = b >> 4, r2 = b & 15;
        float Do = 0;
#pragma unroll
        for (int s = 0; s < 4; ++s) Do += sD[s][mm][0][r2 * 8 + jj];
        int jcol = cta * 8 + jj;
        out[(size_t)b * NSTEPS * 1024 + (size_t)(NSTEPS - 1) * 1024 + jcol] = Do + lin_b[jcol];
    }
}

extern "C" void kernel_launch(void* const* d_in, const int* in_sizes, int n_in,
                              void* d_out, int out_size) {
    (void)in_sizes; (void)n_in; (void)out_size;
    const int*   y          = (const int*)  d_in[0];
    // d_in[1] = U (unused by the reference math)
    const float* embed      = (const float*)d_in[2];
    const float* W_ih       = (const float*)d_in[3];
    const float* W_hh       = (const float*)d_in[4];
    const float* b_ih       = (const float*)d_in[5];
    const float* b_hh       = (const float*)d_in[6];
    const float* init_state = (const float*)d_in[7];
    const float* lin_W      = (const float*)d_in[8];
    const float* lin_b      = (const float*)d_in[9];
    float* out = (float*)d_out;

    decoder_kernel<<<NCTA, NTHR>>>(y, embed, W_ih, W_hh, b_ih, b_hh,
                                   init_state, lin_W, lin_b, out);
}

// round 9
// speedup vs baseline: 8.3880x; 1.2279x over previous
#include <cuda_runtime.h>
#include <cuda_fp16.h>

#define NV     101          // tokens incl. start symbol (start = 100)
#define UMX    256
#define NSTEPS 257
#define G3     3072
#define NCTA   128
#define NTHR   512

typedef unsigned u32;

// ---------------- static device scratch (no runtime allocation) ----------------
// Fragment-packed fp16 hi/lo weights.
// g_W0p: phase A (K=1024): n-rows 0..3071 = W_hh layer0 (r,z,n), 3072..4095 = lin_W.
//   [ntile(512)][ktile(64)][lane(32)] : uint4 = {Whi.b0, Whi.b1, Wlo.b0, Wlo.b1}
__device__ __align__(16) uint4 g_W0p[512 * 64 * 32];            // 16 MB
// g_W12p: layers 1,2 (K=2048): per layer n-row q*1024+j:
//   q=0:[Wih_r|Whh_r] q=1:[Wih_z|Whh_z] q=2:[Wih_n|0] q=3:[0|Whh_n]
//   [layer(2)][ntile(512)][ktile(128)][lane(32)]
__device__ __align__(16) uint4 g_W12p[2 * 512 * 128 * 32];      // 64 MB
// Fragment-packed fp16 activations (single plane): [l(3)][par(2)][mtile(4)][ktile(128)][lane(32)]
//   l=0: cols 0..1023 = h0; l=1,2: cols 0..1023 = x, 1024..2047 = h_prev
__device__ __align__(16) uint4 g_A[3 * 2 * 4 * 128 * 32];       // 1.5 MB
__device__ float g_T[NV * G3];          // layer0 gi table (incl b_ih0), fp32
__device__ float g_stf[3 * 64 * 1024];  // fp32 states [l][b][j]
__device__ unsigned g_bar;

// ---------------- grid barrier (128 CTAs, 1/SM, co-resident) ----------------
__device__ __forceinline__ void gridbar() {
    __threadfence();
    __syncthreads();
    if (threadIdx.x == 0) {
        unsigned ticket = atomicAdd(&g_bar, 1u) + 1u;
        unsigned target = ((ticket + NCTA - 1u) / NCTA) * NCTA;
        while (*((volatile unsigned*)&g_bar) < target) { __nanosleep(32); }
    }
    __syncthreads();
    __threadfence();
}

__device__ __forceinline__ float sigm(float t) { return 1.0f / (1.0f + expf(-t)); }

// split fp32 -> (hi, lo) fp16 bit patterns
__device__ __forceinline__ void sph(float w, u32& hb, u32& lb) {
    __half h = __float2half_rn(w);
    hb = (u32)__half_as_ushort(h);
    lb = (u32)__half_as_ushort(__float2half_rn(w - __half2float(h)));
}
__device__ __forceinline__ uint4 pack4h(float a, float b, float c, float d) {
    u32 ah, al, bh, bl, ch, cl, dh, dl;
    sph(a, ah, al); sph(b, bh, bl); sph(c, ch, cl); sph(d, dh, dl);
    uint4 v;
    v.x = ah | (bh << 16);   // hi b0 (k0, k0+1)
    v.y = ch | (dh << 16);   // hi b1 (k0+8, k0+9)
    v.z = al | (bl << 16);   // lo b0
    v.w = cl | (dl << 16);   // lo b1
    return v;
}

// A-buffer offset (uint4 units, excluding lane)
__device__ __forceinline__ size_t aoff(int l, int par, int mt, int kt) {
    return (size_t)((((l * 2 + par) * 4 + mt) * 128 + kt)) * 32;
}
// Write activation element (b, c) as fp16 into fragment layout
__device__ __forceinline__ void storeA(int l, int par, int b, int c, float v) {
    int mt = b >> 4, mr = b & 15, kt = c >> 4, kk = c & 15;
    int lane = (mr & 7) * 4 + ((kk & 7) >> 1);
    int slot = (mr >> 3) + ((kk >> 3) << 1);
    __half* p = (__half*)(g_A + aoff(l, par, mt, kt) + lane);
    p[slot * 2 + (kk & 1)] = __float2half_rn(v);
}

// ---------------- mma.m16n8k16 fp16 ----------------
__device__ __forceinline__ void mma_f16(float* d, const uint4& a, u32 b0, u32 b1) {
    asm volatile(
        "mma.sync.aligned.m16n8k16.row.col.f32.f16.f16.f32 "
        "{%0,%1,%2,%3}, {%4,%5,%6,%7}, {%8,%9}, {%0,%1,%2,%3};"
        : "+f"(d[0]), "+f"(d[1]), "+f"(d[2]), "+f"(d[3])
        : "r"(a.x), "r"(a.y), "r"(a.z), "r"(a.w), "r"(b0), "r"(b1));
}
// 2-chain combine + store 16x8 tile into smem slab (float[128])
__device__ __forceinline__ void stD2(float* base, int rr, int cc,
                                     const float* d0, const float* d1) {
    base[rr * 8 + cc]           = d0[0] + d1[0];
    base[rr * 8 + cc + 1]       = d0[1] + d1[1];
    base[(rr + 8) * 8 + cc]     = d0[2] + d1[2];
    base[(rr + 8) * 8 + cc + 1] = d0[3] + d1[3];
}

// ================================================================================
__global__ void __launch_bounds__(NTHR, 1)
decoder_kernel(const int*   __restrict__ y,
               const float* __restrict__ embed,
               const float* __restrict__ W_ih,
               const float* __restrict__ W_hh,
               const float* __restrict__ b_ih,
               const float* __restrict__ b_hh,
               const float* __restrict__ init_state,
               const float* __restrict__ lin_W,
               const float* __restrict__ lin_b,
               float*       __restrict__ out)
{
    const int tid  = threadIdx.x;
    const int lane = tid & 31;
    const int wid  = tid >> 5;          // 0..15
    const int mwA  = wid & 3;           // phase A: m-tile
    const int ksA  = wid >> 2;          // phase A: k-slice 0..3 (16 ktiles each)
    const int mpB  = wid & 1;           // B/C: m-half (mtiles {0,1} or {2,3})
    const int ksB  = wid >> 1;          // B/C: k-slice 0..7 (16 ktiles each)
    const int cta  = blockIdx.x;
    const int gt   = cta * NTHR + tid;
    const int GS   = NCTA * NTHR;
    const int rr   = lane >> 2, cc = (lane & 3) << 1;

    __shared__ float sbuf[12288];       // exactly 48 KB reduction buffer
    // phase A view: [s(4)][mt(4)][q(4)][128]
    #define SA(s, mt, q) (sbuf + (((s) * 4 + (mt)) * 4 + (q)) * 128)
    // B/C view: [s(8)][mt(4)][g(3)][128]; g=2 holds i_n for s<4, h_n for s>=4
    #define SB(s, mt, g) (sbuf + (((s) * 4 + (mt)) * 3 + (g)) * 128)

    // ================= PROLOGUE =================
    for (int idx = gt; idx < 512 * 64 * 32; idx += GS) {
        int ln = idx & 31, t = (idx >> 5) & 63, NT = idx >> 11;
        int n  = NT * 8 + (ln >> 2);
        int k0 = t * 16 + ((ln & 3) << 1);
        const float* src = (n < 3072) ? (W_hh + (size_t)n * 1024)
                                      : (lin_W + (size_t)(n - 3072) * 1024);
        g_W0p[idx] = pack4h(src[k0], src[k0 + 1], src[k0 + 8], src[k0 + 9]);
    }
    for (int idx = gt; idx < 2 * 512 * 128 * 32; idx += GS) {
        int ln = idx & 31, t = (idx >> 5) & 127, NT = (idx >> 12) & 511, ll = idx >> 21;
        int n  = NT * 8 + (ln >> 2);
        int qq = n >> 10, jj = n & 1023;
        int k0 = t * 16 + ((ln & 3) << 1);
        int lay = ll + 1;
        float w[4];
#pragma unroll
        for (int i = 0; i < 4; ++i) {
            int k = k0 + ((i >> 1) << 3) + (i & 1);   // k0, k0+1, k0+8, k0+9
            float v = 0.0f;
            if (qq < 2) {
                v = (k < 1024) ? W_ih[((size_t)lay * 3072 + qq * 1024 + jj) * 1024 + k]
                               : W_hh[((size_t)lay * 3072 + qq * 1024 + jj) * 1024 + k - 1024];
            } else if (qq == 2) {
                if (k < 1024) v = W_ih[((size_t)lay * 3072 + 2048 + jj) * 1024 + k];
            } else {
                if (k >= 1024) v = W_hh[((size_t)lay * 3072 + 2048 + jj) * 1024 + k - 1024];
            }
            w[i] = v;
        }
        g_W12p[idx] = pack4h(w[0], w[1], w[2], w[3]);
    }
    // fp32 token table: T[v][row] = embed[v] . W_ih0[row] + b_ih0[row]
    for (int idx = gt; idx < 3072 * 128; idx += GS) {
        int row = idx >> 7, v = idx & 127;
        if (v < NV) {
            const float* e = embed + (size_t)v * 1024;
            const float* w = W_ih + (size_t)row * 1024;
            float a0 = 0, a1 = 0, a2 = 0, a3 = 0;
            for (int k = 0; k < 1024; k += 4) {
                a0 += e[k] * w[k];         a1 += e[k + 1] * w[k + 1];
                a2 += e[k + 2] * w[k + 2]; a3 += e[k + 3] * w[k + 3];
            }
            g_T[v * G3 + row] = (a0 + a1) + (a2 + a3) + b_ih[row];
        }
    }
    for (int idx = gt; idx < 3 * 64 * 1024; idx += GS) {
        int l = idx >> 16, r = idx & 65535, b = r >> 10, j = r & 1023;
        float v = init_state[l * 1024 + j];
        g_stf[idx] = v;
        storeA(l, 0, b, (l == 0) ? j : (1024 + j), v);
    }
    gridbar();

    // ================= STEP LOOP =================
    for (int u = 0; u < NSTEPS; ++u) {
        const int par = u & 1;

        // ----- phase A: layer0 h-GEMM (r,z,n on h0) + lin of u-1 (on h2), K=1024 -----
        {
            const int t0 = ksA * 16;
            const uint4* A0 = g_A + aoff(0, par, mwA, t0) + lane;
            const uint4* A2 = g_A + aoff(2, par, mwA, 64 + t0) + lane;
            const uint4* B0 = g_W0p + ((size_t)(0 * 128 + cta) * 64 + t0) * 32 + lane;
            const uint4* B1 = g_W0p + ((size_t)(1 * 128 + cta) * 64 + t0) * 32 + lane;
            const uint4* B2 = g_W0p + ((size_t)(2 * 128 + cta) * 64 + t0) * 32 + lane;
            const uint4* B3 = g_W0p + ((size_t)(3 * 128 + cta) * 64 + t0) * 32 + lane;
            float d0a[4] = {}, d0b[4] = {}, d1a[4] = {}, d1b[4] = {};
            float d2a[4] = {}, d2b[4] = {}, d3a[4] = {}, d3b[4] = {};
#pragma unroll 2
            for (int i = 0; i < 16; ++i) {
                uint4 a = A0[i * 32], c = A2[i * 32];
                uint4 b0 = B0[i * 32], b1 = B1[i * 32], b2 = B2[i * 32], b3 = B3[i * 32];
                mma_f16(d0a, a, b0.x, b0.y); mma_f16(d0b, a, b0.z, b0.w);
                mma_f16(d1a, a, b1.x, b1.y); mma_f16(d1b, a, b1.z, b1.w);
                mma_f16(d2a, a, b2.x, b2.y); mma_f16(d2b, a, b2.z, b2.w);
                mma_f16(d3a, c, b3.x, b3.y); mma_f16(d3b, c, b3.z, b3.w);
            }
            stD2(SA(ksA, mwA, 0), rr, cc, d0a, d0b);
            stD2(SA(ksA, mwA, 1), rr, cc, d1a, d1b);
            stD2(SA(ksA, mwA, 2), rr, cc, d2a, d2b);
            stD2(SA(ksA, mwA, 3), rr, cc, d3a, d3b);
        }
        __syncthreads();
        {   // epilogue A: GRU layer0 + out[u-1]
            int b = tid >> 3, jj = tid & 7, mm = b >> 4, r2 = b & 15;
            float Dr = 0, Dz = 0, Dn = 0, Do = 0;
#pragma unroll
            for (int s = 0; s < 4; ++s) {
                Dr += SA(s, mm, 0)[r2 * 8 + jj];
                Dz += SA(s, mm, 1)[r2 * 8 + jj];
                Dn += SA(s, mm, 2)[r2 * 8 + jj];
                Do += SA(s, mm, 3)[r2 * 8 + jj];
            }
            int jcol = cta * 8 + jj;
            int tok = (u == 0) ? (NV - 1) : y[b * UMX + (u - 1)];
            const float* Tv = g_T + (size_t)tok * G3;
            float r = sigm(Tv[jcol] + Dr + b_hh[jcol]);
            float z = sigm(Tv[1024 + jcol] + Dz + b_hh[1024 + jcol]);
            float n = tanhf(Tv[2048 + jcol] + r * (Dn + b_hh[2048 + jcol]));
            float hp = g_stf[b * 1024 + jcol];
            float h = (1.0f - z) * n + z * hp;
            g_stf[b * 1024 + jcol] = h;
            storeA(1, par, b, jcol, h);          // x for layer1 this step
            storeA(0, par ^ 1, b, jcol, h);      // h0 for next step
            if (u > 0)
                out[(size_t)b * NSTEPS * 1024 + (size_t)(u - 1) * 1024 + jcol] = Do + lin_b[jcol];
        }
        gridbar();

        // ----- phases B, C: layers 1, 2 (K=2048; warp = (m-half, k-slice of 8)) -----
#pragma unroll 1
        for (int l = 1; l <= 2; ++l) {
            {
                const int t0  = ksB * 16;
                const int g2q = 2 + (ksB >> 2);        // i_n for ks<4, h_n for ks>=4
                const int mt0 = mpB * 2;
                const uint4* A  = g_A + aoff(l, par, mt0, t0) + lane;
                const uint4* B0 = g_W12p + ((size_t)((l - 1) * 512 + 0 * 128 + cta) * 128 + t0) * 32 + lane;
                const uint4* B1 = g_W12p + ((size_t)((l - 1) * 512 + 1 * 128 + cta) * 128 + t0) * 32 + lane;
                const uint4* B2 = g_W12p + ((size_t)((l - 1) * 512 + g2q * 128 + cta) * 128 + t0) * 32 + lane;
                float m0g0a[4] = {}, m0g0b[4] = {}, m0g1a[4] = {}, m0g1b[4] = {};
                float m0g2a[4] = {}, m0g2b[4] = {};
                float m1g0a[4] = {}, m1g0b[4] = {}, m1g1a[4] = {}, m1g1b[4] = {};
                float m1g2a[4] = {}, m1g2b[4] = {};
#pragma unroll 2
                for (int i = 0; i < 16; ++i) {
                    uint4 a0 = A[i * 32], a1 = A[i * 32 + 128 * 32];
                    uint4 b0 = B0[i * 32], b1 = B1[i * 32], b2 = B2[i * 32];
                    mma_f16(m0g0a, a0, b0.x, b0.y); mma_f16(m0g0b, a0, b0.z, b0.w);
                    mma_f16(m0g1a, a0, b1.x, b1.y); mma_f16(m0g1b, a0, b1.z, b1.w);
                    mma_f16(m0g2a, a0, b2.x, b2.y); mma_f16(m0g2b, a0, b2.z, b2.w);
                    mma_f16(m1g0a, a1, b0.x, b0.y); mma_f16(m1g0b, a1, b0.z, b0.w);
                    mma_f16(m1g1a, a1, b1.x, b1.y); mma_f16(m1g1b, a1, b1.z, b1.w);
                    mma_f16(m1g2a, a1, b2.x, b2.y); mma_f16(m1g2b, a1, b2.z, b2.w);
                }
                stD2(SB(ksB, mt0, 0), rr, cc, m0g0a, m0g0b);
                stD2(SB(ksB, mt0, 1), rr, cc, m0g1a, m0g1b);
                stD2(SB(ksB, mt0, 2), rr, cc, m0g2a, m0g2b);
                stD2(SB(ksB, mt0 + 1, 0), rr, cc, m1g0a, m1g0b);
                stD2(SB(ksB, mt0 + 1, 1), rr, cc, m1g1a, m1g1b);
                stD2(SB(ksB, mt0 + 1, 2), rr, cc, m1g2a, m1g2b);
            }
            __syncthreads();
            {   // epilogue: GRU layer l
                int b = tid >> 3, jj = tid & 7, mm = b >> 4, r2 = b & 15;
                float Gr = 0, Gz = 0, Gi = 0, Gh = 0;
#pragma unroll
                for (int s = 0; s < 8; ++s) {
                    Gr += SB(s, mm, 0)[r2 * 8 + jj];
                    Gz += SB(s, mm, 1)[r2 * 8 + jj];
                }
#pragma unroll
                for (int s = 0; s < 4; ++s) Gi += SB(s, mm, 2)[r2 * 8 + jj];
#pragma unroll
                for (int s = 4; s < 8; ++s) Gh += SB(s, mm, 2)[r2 * 8 + jj];
                int jcol = cta * 8 + jj;
                const float* bi  = b_ih + l * G3;
                const float* bhv = b_hh + l * G3;
                float r = sigm(Gr + bi[jcol] + bhv[jcol]);
                float z = sigm(Gz + bi[1024 + jcol] + bhv[1024 + jcol]);
                float n = tanhf(Gi + bi[2048 + jcol] + r * (Gh + bhv[2048 + jcol]));
                float hp = g_stf[(l * 64 + b) * 1024 + jcol];
                float h = (1.0f - z) * n + z * hp;
                g_stf[(l * 64 + b) * 1024 + jcol] = h;
                if (l == 1) {
                    storeA(2, par, b, jcol, h);              // x for layer2 this step
                    storeA(1, par ^ 1, b, 1024 + jcol, h);   // h1 next step
                } else {
                    storeA(2, par ^ 1, b, 1024 + jcol, h);   // h2: lin + layer2 next step
                }
            }
            gridbar();
        }
    }

    // ================= FINAL OUTPUT (u = NSTEPS-1) =================
    {
        const int t0 = ksA * 16;
        const uint4* A2 = g_A + aoff(2, NSTEPS & 1, mwA, 64 + t0) + lane;
        const uint4* B3 = g_W0p + ((size_t)(384 + cta) * 64 + t0) * 32 + lane;
        float da[4] = {}, db[4] = {};
#pragma unroll 2
        for (int i = 0; i < 16; ++i) {
            uint4 c = A2[i * 32], b3 = B3[i * 32];
            mma_f16(da, c, b3.x, b3.y);
            mma_f16(db, c, b3.z, b3.w);
        }
        stD2(SA(ksA, mwA, 0), rr, cc, da, db);
    }
    __syncthreads();
    {
        int b = tid >> 3, jj = tid & 7, mm = b >> 4, r2 = b & 15;
        float Do = 0;
#pragma unroll
        for (int s = 0; s < 4; ++s) Do += SA(s, mm, 0)[r2 * 8 + jj];
        int jcol = cta * 8 + jj;
        out[(size_t)b * NSTEPS * 1024 + (size_t)(NSTEPS - 1) * 1024 + jcol] = Do + lin_b[jcol];
    }
    #undef SA
    #undef SB
}

extern "C" void kernel_launch(void* const* d_in, const int* in_sizes, int n_in,
                              void* d_out, int out_size) {
    (void)in_sizes; (void)n_in; (void)out_size;
    const int*   y          = (const int*)  d_in[0];
    // d_in[1] = U (unused by the reference math)
    const float* embed      = (const float*)d_in[2];
    const float* W_ih       = (const float*)d_in[3];
    const float* W_hh       = (const float*)d_in[4];
    const float* b_ih       = (const float*)d_in[5];
    const float* b_hh       = (const float*)d_in[6];
    const float* init_state = (const float*)d_in[7];
    const float* lin_W      = (const float*)d_in[8];
    const float* lin_b      = (const float*)d_in[9];
    float* out = (float*)d_out;

    decoder_kernel<<<NCTA, NTHR>>>(y, embed, W_ih, W_hh, b_ih, b_hh,
                                   init_state, lin_W, lin_b, out);
}